// round 1
// baseline (speedup 1.0000x reference)
#include <cuda_runtime.h>

#define BB 256
#define DD 5120
#define NN 16
#define RR 160
#define JJ 192          // RR + 32 (B/C projections)
#define KSPLIT 10
#define KCH (DD / KSPLIT)

// Scratch (device globals — no allocations allowed)
__device__ float g_P[KSPLIT * BB * JJ];   // split-K partials of x @ [W_x_dt | W_BC]
__device__ float g_T[BB * JJ];            // reduced projections

__device__ __forceinline__ float ex2f(float v) {
    float r;
    asm("ex2.approx.ftz.f32 %0, %1;" : "=f"(r) : "f"(v));
    return r;
}

// ---------------------------------------------------------------------------
// Kernel 1: split-K GEMM. P[ks] += x[:, ksplit chunk] @ [W_x_dt | W_BC]
// Tile 64(M) x 64(N), BK=16, 256 threads, 4x4 micro-tile. Grid (4, 3, 10).
// ---------------------------------------------------------------------------
__global__ __launch_bounds__(256) void mamba_proj_kernel(
    const float* __restrict__ x, const float* __restrict__ Wx,
    const float* __restrict__ Wbc)
{
    __shared__ float As[64][16];   // [m][k]
    __shared__ float Bs[16][64];   // [k][n]
    const int m0 = blockIdx.x * 64;
    const int n0 = blockIdx.y * 64;
    const int k0 = blockIdx.z * KCH;
    const int tid = threadIdx.x;
    const int tx = tid & 15, ty = tid >> 4;
    const int lr = tid >> 2, lc = (tid & 3) << 2;    // A tile load coords
    const int bk = tid >> 4, bc = (tid & 15) << 2;   // B tile load coords

    float acc[4][4] = {};

    for (int kc = 0; kc < KCH; kc += 16) {
        const int k = k0 + kc;
        float4 av = *(const float4*)&x[(size_t)(m0 + lr) * DD + k + lc];
        const int kb = k + bk;
        const int j = n0 + bc;
        float4 bv;
        if (j < RR) bv = *(const float4*)&Wx[(size_t)kb * RR + j];
        else        bv = *(const float4*)&Wbc[(size_t)kb * 32 + (j - RR)];
        __syncthreads();
        *(float4*)&As[lr][lc] = av;
        *(float4*)&Bs[bk][bc] = bv;
        __syncthreads();
#pragma unroll
        for (int kk = 0; kk < 16; kk++) {
            float a[4];
#pragma unroll
            for (int i = 0; i < 4; i++) a[i] = As[ty * 4 + i][kk];
            float4 b4 = *(const float4*)&Bs[kk][tx * 4];
            float bw[4] = {b4.x, b4.y, b4.z, b4.w};
#pragma unroll
            for (int i = 0; i < 4; i++)
#pragma unroll
                for (int jq = 0; jq < 4; jq++)
                    acc[i][jq] = fmaf(a[i], bw[jq], acc[i][jq]);
        }
    }
    float* dst = &g_P[(size_t)blockIdx.z * (BB * JJ)];
#pragma unroll
    for (int i = 0; i < 4; i++) {
        float4 v = make_float4(acc[i][0], acc[i][1], acc[i][2], acc[i][3]);
        *(float4*)&dst[(size_t)(m0 + ty * 4 + i) * JJ + n0 + tx * 4] = v;
    }
}

// ---------------------------------------------------------------------------
// Kernel 1r: reduce split-K partials. Grid (BB*JJ/256), 256 threads.
// ---------------------------------------------------------------------------
__global__ __launch_bounds__(256) void mamba_reduce_kernel()
{
    const int idx = blockIdx.x * 256 + threadIdx.x;
    float s = 0.f;
#pragma unroll
    for (int ks = 0; ks < KSPLIT; ks++) s += g_P[ks * (BB * JJ) + idx];
    g_T[idx] = s;
}

// ---------------------------------------------------------------------------
// Kernel 2: fused  z = t @ W_dt + b_dt ; dt = softplus(z) ;
//           y = sum_n exp(A*dt)*h0*C  +  dt*x*sum_n(B*C)  +  x
// Tile: 32 (b) x 128 (d). 256 threads, 4x4 micro-tile, strided d mapping.
// Grid (DD/128, BB/32).
// ---------------------------------------------------------------------------
__global__ __launch_bounds__(256) void mamba_ssm_kernel(
    const float* __restrict__ x, const float* __restrict__ h0,
    const float* __restrict__ Wdt, const float* __restrict__ bdt,
    const float* __restrict__ Alog, float* __restrict__ out)
{
    const int d0 = blockIdx.x * 128;
    const int b0 = blockIdx.y * 32;
    const int tid = threadIdx.x;
    const int tdx = tid & 31;     // d lane
    const int tby = tid >> 5;     // 0..7 (b group)

    __shared__ float Ts[32][160];    // t tile
    __shared__ float BCs[32][32];    // B (0..15) and C (16..31) per b
    __shared__ float A2s[16][129];   // -exp(A_log)*log2(e), [n][d], padded
    __shared__ float Ws[16][128];    // W_dt chunk
    __shared__ float bds[128];
    __shared__ float SBC[32];        // sum_n B[b,n]*C[b,n]

    for (int idx = tid; idx < 32 * 160; idx += 256) {
        int b = idx / 160, r = idx - b * 160;
        Ts[b][r] = g_T[(b0 + b) * JJ + r];
    }
    for (int idx = tid; idx < 32 * 32; idx += 256) {
        int b = idx >> 5, j = idx & 31;
        BCs[b][j] = g_T[(b0 + b) * JJ + RR + j];
    }
    for (int idx = tid; idx < 128 * 16; idx += 256) {
        int di = idx >> 4, n = idx & 15;
        A2s[n][di] = -__expf(Alog[(size_t)(d0 + di) * NN + n]) * 1.44269504f;
    }
    if (tid < 128) bds[tid] = bdt[d0 + tid];
    __syncthreads();
    if (tid < 32) {
        float s = 0.f;
#pragma unroll
        for (int n = 0; n < NN; n++) s += BCs[tid][n] * BCs[tid][NN + n];
        SBC[tid] = s;
    }
    // (SBC visibility is guaranteed by the first __syncthreads in the rc loop)

    float acc[4][4] = {};
    const int wr = tid >> 4;          // 0..15
    const int wc = (tid & 15) << 3;   // 0..120
    for (int rc = 0; rc < RR; rc += 16) {
        const float* wsrc = &Wdt[(size_t)(rc + wr) * DD + d0 + wc];
        float4 w0 = *(const float4*)wsrc;
        float4 w1 = *(const float4*)(wsrc + 4);
        __syncthreads();
        *(float4*)&Ws[wr][wc] = w0;
        *(float4*)&Ws[wr][wc + 4] = w1;
        __syncthreads();
#pragma unroll
        for (int rr = 0; rr < 16; rr++) {
            float a[4], w[4];
#pragma unroll
            for (int i = 0; i < 4; i++) a[i] = Ts[tby * 4 + i][rc + rr];
#pragma unroll
            for (int jq = 0; jq < 4; jq++) w[jq] = Ws[rr][tdx + 32 * jq];
#pragma unroll
            for (int i = 0; i < 4; i++)
#pragma unroll
                for (int jq = 0; jq < 4; jq++)
                    acc[i][jq] = fmaf(a[i], w[jq], acc[i][jq]);
        }
    }

    // Epilogue: softplus + SSM update + reduction over n, streaming h0.
#pragma unroll
    for (int jq = 0; jq < 4; jq++) {
        const int dc = tdx + 32 * jq;
        float a2r[16];
#pragma unroll
        for (int n = 0; n < 16; n++) a2r[n] = A2s[n][dc];
        const float bd = bds[dc];
#pragma unroll
        for (int bi = 0; bi < 4; bi++) {
            const int bl = tby * 4 + bi;
            const size_t g = (size_t)(b0 + bl) * DD + d0 + dc;
            const float z = acc[bi][jq] + bd;
            const float dt = fmaxf(z, 0.f) + log1pf(__expf(-fabsf(z)));
            const float xv = x[g];
            const float dtx = dt * xv;
            float yv = fmaf(dtx, SBC[bl], xv);
            const float4* hp = (const float4*)(h0 + g * NN);
#pragma unroll
            for (int q = 0; q < 4; q++) {
                float4 hv = hp[q];
                yv = fmaf(ex2f(a2r[4 * q + 0] * dt) * hv.x, BCs[bl][NN + 4 * q + 0], yv);
                yv = fmaf(ex2f(a2r[4 * q + 1] * dt) * hv.y, BCs[bl][NN + 4 * q + 1], yv);
                yv = fmaf(ex2f(a2r[4 * q + 2] * dt) * hv.z, BCs[bl][NN + 4 * q + 2], yv);
                yv = fmaf(ex2f(a2r[4 * q + 3] * dt) * hv.w, BCs[bl][NN + 4 * q + 3], yv);
            }
            out[g] = yv;
        }
    }
}

// ---------------------------------------------------------------------------
extern "C" void kernel_launch(void* const* d_in, const int* in_sizes, int n_in,
                              void* d_out, int out_size)
{
    const float* x    = (const float*)d_in[0];
    const float* h0   = (const float*)d_in[1];
    const float* Wx   = (const float*)d_in[2];
    const float* Wdt  = (const float*)d_in[3];
    const float* bdt  = (const float*)d_in[4];
    const float* Wbc  = (const float*)d_in[5];
    const float* Alog = (const float*)d_in[6];
    float* out = (float*)d_out;

    mamba_proj_kernel<<<dim3(4, 3, KSPLIT), 256>>>(x, Wx, Wbc);
    mamba_reduce_kernel<<<(BB * JJ) / 256, 256>>>();
    mamba_ssm_kernel<<<dim3(DD / 128, BB / 32), 256>>>(x, h0, Wdt, bdt, Alog, out);
}

// round 2
// speedup vs baseline: 1.1413x; 1.1413x over previous
#include <cuda_runtime.h>

#define BB 256
#define DD 5120
#define NN 16
#define RR 160
#define JJ 192          // RR + 32 (B/C projections)
#define KSPLIT 32
#define KCH (DD / KSPLIT)   // 160

// Scratch (device globals — no allocations allowed)
__device__ float g_P[KSPLIT * BB * JJ];   // split-K partials of x @ [W_x_dt | W_BC]
__device__ float g_T[BB * JJ];            // reduced projections

__device__ __forceinline__ float ex2f(float v) {
    float r;
    asm("ex2.approx.ftz.f32 %0, %1;" : "=f"(r) : "f"(v));
    return r;
}

typedef unsigned long long ull;

__device__ __forceinline__ ull fma2(ull a, ull b, ull c) {
    ull d;
    asm("fma.rn.f32x2 %0, %1, %2, %3;" : "=l"(d) : "l"(a), "l"(b), "l"(c));
    return d;
}
__device__ __forceinline__ ull pack2(float x, float y) {
    ull r;
    asm("mov.b64 %0, {%1, %2};" : "=l"(r) : "f"(x), "f"(y));
    return r;
}
__device__ __forceinline__ float2 unpk(ull v) {
    float2 r;
    asm("mov.b64 {%0, %1}, %2;" : "=f"(r.x), "=f"(r.y) : "l"(v));
    return r;
}

// ---------------------------------------------------------------------------
// Kernel 1: split-K GEMM. P[ks] = x[:, k-chunk] @ [W_x_dt | W_BC]
// Tile 64(M) x 64(N), BK=16, 256 threads, 4x4 micro-tile (packed f32x2).
// Grid (4, 3, 32) = 384 blocks.
// ---------------------------------------------------------------------------
__global__ __launch_bounds__(256) void mamba_proj_kernel(
    const float* __restrict__ x, const float* __restrict__ Wx,
    const float* __restrict__ Wbc)
{
    __shared__ float As[16][68];   // [k][m], padded
    __shared__ float Bs[16][64];   // [k][n]
    const int m0 = blockIdx.x * 64;
    const int n0 = blockIdx.y * 64;
    const int k0 = blockIdx.z * KCH;
    const int tid = threadIdx.x;
    const int tx = tid & 15, ty = tid >> 4;       // micro-tile coords
    const int lr = tid >> 2, lc = (tid & 3) << 2; // A tile load coords
    const int bk = tid >> 4, bc = (tid & 15) << 2;// B tile load coords

    ull acc2[4][2] = {};

    for (int kc = 0; kc < KCH; kc += 16) {
        const int k = k0 + kc;
        float4 av = *(const float4*)&x[(size_t)(m0 + lr) * DD + k + lc];
        const int kb = k + bk;
        const int j = n0 + bc;
        float4 bv;
        if (j < RR) bv = *(const float4*)&Wx[(size_t)kb * RR + j];
        else        bv = *(const float4*)&Wbc[(size_t)kb * 32 + (j - RR)];
        __syncthreads();
        As[lc + 0][lr] = av.x;
        As[lc + 1][lr] = av.y;
        As[lc + 2][lr] = av.z;
        As[lc + 3][lr] = av.w;
        *(float4*)&Bs[bk][bc] = bv;
        __syncthreads();
#pragma unroll
        for (int kk = 0; kk < 16; kk++) {
            float4 a4 = *(const float4*)&As[kk][ty * 4];
            float4 b4 = *(const float4*)&Bs[kk][tx * 4];
            ull b01 = pack2(b4.x, b4.y);
            ull b23 = pack2(b4.z, b4.w);
            float aw[4] = {a4.x, a4.y, a4.z, a4.w};
#pragma unroll
            for (int i = 0; i < 4; i++) {
                ull ap = pack2(aw[i], aw[i]);
                acc2[i][0] = fma2(ap, b01, acc2[i][0]);
                acc2[i][1] = fma2(ap, b23, acc2[i][1]);
            }
        }
    }
    float* dst = &g_P[(size_t)blockIdx.z * (BB * JJ)];
#pragma unroll
    for (int i = 0; i < 4; i++) {
        float2 p0 = unpk(acc2[i][0]);
        float2 p1 = unpk(acc2[i][1]);
        *(float4*)&dst[(size_t)(m0 + ty * 4 + i) * JJ + n0 + tx * 4] =
            make_float4(p0.x, p0.y, p1.x, p1.y);
    }
}

// ---------------------------------------------------------------------------
// Kernel 1r: reduce split-K partials. Grid (BB*JJ/256), 256 threads.
// ---------------------------------------------------------------------------
__global__ __launch_bounds__(256) void mamba_reduce_kernel()
{
    const int idx = blockIdx.x * 256 + threadIdx.x;
    float s = 0.f;
#pragma unroll
    for (int ks = 0; ks < KSPLIT; ks++) s += g_P[ks * (BB * JJ) + idx];
    g_T[idx] = s;
}

// ---------------------------------------------------------------------------
// Kernel 2: fused  z = t @ W_dt + b_dt ; dt = softplus(z) ;
//           y = sum_n exp(A*dt)*h0*C  +  dt*x*sum_n(B*C)  +  x
// Tile: 32 (b) x 128 (d). 256 threads, micro-tile 4b x 4 CONSECUTIVE d.
// Thread owns d = d0 + tdx*4 + {0..3}, b = b0 + tby*4 + {0..3}.
// Grid (DD/128, BB/32) = (40, 8).
// ---------------------------------------------------------------------------
__global__ __launch_bounds__(256) void mamba_ssm_kernel(
    const float* __restrict__ x, const float* __restrict__ h0,
    const float* __restrict__ Wdt, const float* __restrict__ bdt,
    const float* __restrict__ Alog, float* __restrict__ out)
{
    const int d0 = blockIdx.x * 128;
    const int b0 = blockIdx.y * 32;
    const int tid = threadIdx.x;
    const int tdx = tid & 31;     // d lane (owns 4 consecutive d)
    const int tby = tid >> 5;     // 0..7 (b group)

    __shared__ float Ts[32][160];    // t tile [b][r] (reads are warp-broadcast)
    __shared__ float BCs[32][32];    // B (0..15) and C (16..31) per b
    __shared__ float A2s[16][128];   // -exp(A_log)*log2(e), [n][pd], PERMUTED d
    __shared__ float Ws[16][128];    // W_dt chunk
    __shared__ float bds[128];       // permuted d
    __shared__ float SBC[32];        // sum_n B[b,n]*C[b,n]

    for (int idx = tid; idx < 32 * 160; idx += 256) {
        int b = idx / 160, r = idx - b * 160;
        Ts[b][r] = g_T[(b0 + b) * JJ + r];
    }
    for (int idx = tid; idx < 32 * 32; idx += 256) {
        int b = idx >> 5, j = idx & 31;
        BCs[b][j] = g_T[(b0 + b) * JJ + RR + j];
    }
    // Permute d: pd = (di & 3)*32 + (di >> 2). Thread (tdx) reading lane
    // pd = dd*32 + tdx maps to global d = d0 + tdx*4 + dd (conflict-free).
    for (int idx = tid; idx < 128 * 16; idx += 256) {
        int di = idx >> 4, n = idx & 15;
        int pd = ((di & 3) << 5) + (di >> 2);
        A2s[n][pd] = -__expf(Alog[(size_t)(d0 + di) * NN + n]) * 1.44269504f;
    }
    if (tid < 128) {
        int pd = ((tid & 3) << 5) + (tid >> 2);
        bds[pd] = bdt[d0 + tid];
    }
    __syncthreads();
    if (tid < 32) {
        float s = 0.f;
#pragma unroll
        for (int n = 0; n < NN; n++) s += BCs[tid][n] * BCs[tid][NN + n];
        SBC[tid] = s;
    }
    // SBC visibility guaranteed by the first __syncthreads in the rc loop.

    ull acc2[4][2] = {};
    const int wr = tid >> 4;          // 0..15
    const int wc = (tid & 15) << 3;   // 0..120
    for (int rc = 0; rc < RR; rc += 16) {
        const float* wsrc = &Wdt[(size_t)(rc + wr) * DD + d0 + wc];
        float4 w0 = *(const float4*)wsrc;
        float4 w1 = *(const float4*)(wsrc + 4);
        __syncthreads();
        *(float4*)&Ws[wr][wc] = w0;
        *(float4*)&Ws[wr][wc + 4] = w1;
        __syncthreads();
#pragma unroll
        for (int rr = 0; rr < 16; rr++) {
            float4 w4 = *(const float4*)&Ws[rr][tdx * 4];  // conflict-free
            ull w01 = pack2(w4.x, w4.y);
            ull w23 = pack2(w4.z, w4.w);
#pragma unroll
            for (int bi = 0; bi < 4; bi++) {
                float a = Ts[tby * 4 + bi][rc + rr];       // warp broadcast
                ull ap = pack2(a, a);
                acc2[bi][0] = fma2(ap, w01, acc2[bi][0]);
                acc2[bi][1] = fma2(ap, w23, acc2[bi][1]);
            }
        }
    }

    // Unpack GEMM result: accf[bi][dd], d = d0 + tdx*4 + dd
    float accf[4][4];
#pragma unroll
    for (int bi = 0; bi < 4; bi++) {
        float2 p0 = unpk(acc2[bi][0]);
        float2 p1 = unpk(acc2[bi][1]);
        accf[bi][0] = p0.x; accf[bi][1] = p0.y;
        accf[bi][2] = p1.x; accf[bi][3] = p1.y;
    }

    // Prefetch x (float4 per b-row, covers this thread's 4 d)
    float4 xq[4];
#pragma unroll
    for (int bi = 0; bi < 4; bi++)
        xq[bi] = *(const float4*)&x[(size_t)(b0 + tby * 4 + bi) * DD + d0 + tdx * 4];

    // Epilogue: softplus + SSM update + reduction over n, streaming h0.
#pragma unroll
    for (int dd = 0; dd < 4; dd++) {
        float a2r[16];
#pragma unroll
        for (int n = 0; n < 16; n++) a2r[n] = A2s[n][dd * 32 + tdx];  // conflict-free
        const float bd = bds[dd * 32 + tdx];
#pragma unroll
        for (int bi = 0; bi < 4; bi++) {
            const int bl = tby * 4 + bi;
            const float z = accf[bi][dd] + bd;
            const float dt = fmaxf(z, 0.f) + log1pf(__expf(-fabsf(z)));
            const float xv = ((const float*)&xq[bi])[dd];
            const size_t g = (size_t)(b0 + bl) * DD + d0 + tdx * 4 + dd;
            const float4* hp = (const float4*)(h0 + g * NN);
            float4 h0v = hp[0], h1v = hp[1], h2v = hp[2], h3v = hp[3];  // MLP=4
            // 4 independent accumulators to break the serial FMA chain
            float y0, y1, y2, y3;
            y0 = ex2f(a2r[0]  * dt) * h0v.x * BCs[bl][NN + 0];
            y1 = ex2f(a2r[1]  * dt) * h0v.y * BCs[bl][NN + 1];
            y2 = ex2f(a2r[2]  * dt) * h0v.z * BCs[bl][NN + 2];
            y3 = ex2f(a2r[3]  * dt) * h0v.w * BCs[bl][NN + 3];
            y0 = fmaf(ex2f(a2r[4]  * dt) * h1v.x, BCs[bl][NN + 4],  y0);
            y1 = fmaf(ex2f(a2r[5]  * dt) * h1v.y, BCs[bl][NN + 5],  y1);
            y2 = fmaf(ex2f(a2r[6]  * dt) * h1v.z, BCs[bl][NN + 6],  y2);
            y3 = fmaf(ex2f(a2r[7]  * dt) * h1v.w, BCs[bl][NN + 7],  y3);
            y0 = fmaf(ex2f(a2r[8]  * dt) * h2v.x, BCs[bl][NN + 8],  y0);
            y1 = fmaf(ex2f(a2r[9]  * dt) * h2v.y, BCs[bl][NN + 9],  y1);
            y2 = fmaf(ex2f(a2r[10] * dt) * h2v.z, BCs[bl][NN + 10], y2);
            y3 = fmaf(ex2f(a2r[11] * dt) * h2v.w, BCs[bl][NN + 11], y3);
            y0 = fmaf(ex2f(a2r[12] * dt) * h3v.x, BCs[bl][NN + 12], y0);
            y1 = fmaf(ex2f(a2r[13] * dt) * h3v.y, BCs[bl][NN + 13], y1);
            y2 = fmaf(ex2f(a2r[14] * dt) * h3v.z, BCs[bl][NN + 14], y2);
            y3 = fmaf(ex2f(a2r[15] * dt) * h3v.w, BCs[bl][NN + 15], y3);
            float yv = fmaf(dt * xv, SBC[bl], xv);
            accf[bi][dd] = yv + ((y0 + y1) + (y2 + y3));
        }
    }

    // Vectorized output stores (4 consecutive d per thread)
#pragma unroll
    for (int bi = 0; bi < 4; bi++) {
        *(float4*)&out[(size_t)(b0 + tby * 4 + bi) * DD + d0 + tdx * 4] =
            make_float4(accf[bi][0], accf[bi][1], accf[bi][2], accf[bi][3]);
    }
}

// ---------------------------------------------------------------------------
extern "C" void kernel_launch(void* const* d_in, const int* in_sizes, int n_in,
                              void* d_out, int out_size)
{
    const float* x    = (const float*)d_in[0];
    const float* h0   = (const float*)d_in[1];
    const float* Wx   = (const float*)d_in[2];
    const float* Wdt  = (const float*)d_in[3];
    const float* bdt  = (const float*)d_in[4];
    const float* Wbc  = (const float*)d_in[5];
    const float* Alog = (const float*)d_in[6];
    float* out = (float*)d_out;

    mamba_proj_kernel<<<dim3(4, 3, KSPLIT), 256>>>(x, Wx, Wbc);
    mamba_reduce_kernel<<<(BB * JJ) / 256, 256>>>();
    mamba_ssm_kernel<<<dim3(DD / 128, BB / 32), 256>>>(x, h0, Wdt, bdt, Alog, out);
}

// round 3
// speedup vs baseline: 1.4462x; 1.2671x over previous
#include <cuda_runtime.h>

#define BB 256
#define DD 5120
#define NN 16
#define RR 160
#define JJ 192          // RR + 32 (B/C projections)
#define KSPLIT 64
#define KCH (DD / KSPLIT)   // 80

// Scratch (device globals — no allocations allowed)
__device__ float g_P[KSPLIT * BB * JJ];   // split-K partials (12.6 MB)
__device__ float g_T[BB * JJ];            // reduced projections

__device__ __forceinline__ float ex2f(float v) {
    float r;
    asm("ex2.approx.ftz.f32 %0, %1;" : "=f"(r) : "f"(v));
    return r;
}

typedef unsigned long long ull;

__device__ __forceinline__ ull fma2(ull a, ull b, ull c) {
    ull d;
    asm("fma.rn.f32x2 %0, %1, %2, %3;" : "=l"(d) : "l"(a), "l"(b), "l"(c));
    return d;
}
__device__ __forceinline__ ull pack2(float x, float y) {
    ull r;
    asm("mov.b64 %0, {%1, %2};" : "=l"(r) : "f"(x), "f"(y));
    return r;
}
__device__ __forceinline__ float2 unpk(ull v) {
    float2 r;
    asm("mov.b64 {%0, %1}, %2;" : "=f"(r.x), "=f"(r.y) : "l"(v));
    return r;
}

// ---------------------------------------------------------------------------
// Kernel 1: split-K GEMM. P[ks] = x[:, k-chunk] @ [W_x_dt | W_BC]
// Tile 64(M) x 64(N), BK=16, 256 threads, 4x4 micro-tile (packed f32x2).
// Grid (4, 3, 64) = 768 blocks (~5.2/SM).
// ---------------------------------------------------------------------------
__global__ __launch_bounds__(256) void mamba_proj_kernel(
    const float* __restrict__ x, const float* __restrict__ Wx,
    const float* __restrict__ Wbc)
{
    __shared__ float As[16][68];   // [k][m], padded
    __shared__ float Bs[16][64];   // [k][n]
    const int m0 = blockIdx.x * 64;
    const int n0 = blockIdx.y * 64;
    const int k0 = blockIdx.z * KCH;
    const int tid = threadIdx.x;
    const int tx = tid & 15, ty = tid >> 4;       // micro-tile coords
    const int lr = tid >> 2, lc = (tid & 3) << 2; // A tile load coords
    const int bk = tid >> 4, bc = (tid & 15) << 2;// B tile load coords

    ull acc2[4][2] = {};

#pragma unroll
    for (int kc = 0; kc < KCH; kc += 16) {
        const int k = k0 + kc;
        float4 av = *(const float4*)&x[(size_t)(m0 + lr) * DD + k + lc];
        const int kb = k + bk;
        const int j = n0 + bc;
        float4 bv;
        if (j < RR) bv = *(const float4*)&Wx[(size_t)kb * RR + j];
        else        bv = *(const float4*)&Wbc[(size_t)kb * 32 + (j - RR)];
        __syncthreads();
        As[lc + 0][lr] = av.x;
        As[lc + 1][lr] = av.y;
        As[lc + 2][lr] = av.z;
        As[lc + 3][lr] = av.w;
        *(float4*)&Bs[bk][bc] = bv;
        __syncthreads();
#pragma unroll
        for (int kk = 0; kk < 16; kk++) {
            float4 a4 = *(const float4*)&As[kk][ty * 4];
            float4 b4 = *(const float4*)&Bs[kk][tx * 4];
            ull b01 = pack2(b4.x, b4.y);
            ull b23 = pack2(b4.z, b4.w);
            float aw[4] = {a4.x, a4.y, a4.z, a4.w};
#pragma unroll
            for (int i = 0; i < 4; i++) {
                ull ap = pack2(aw[i], aw[i]);
                acc2[i][0] = fma2(ap, b01, acc2[i][0]);
                acc2[i][1] = fma2(ap, b23, acc2[i][1]);
            }
        }
    }
    float* dst = &g_P[(size_t)blockIdx.z * (BB * JJ)];
#pragma unroll
    for (int i = 0; i < 4; i++) {
        float2 p0 = unpk(acc2[i][0]);
        float2 p1 = unpk(acc2[i][1]);
        *(float4*)&dst[(size_t)(m0 + ty * 4 + i) * JJ + n0 + tx * 4] =
            make_float4(p0.x, p0.y, p1.x, p1.y);
    }
}

// ---------------------------------------------------------------------------
// Kernel 1r: reduce split-K partials (float4). Grid 48, 256 threads.
// ---------------------------------------------------------------------------
__global__ __launch_bounds__(256) void mamba_reduce_kernel()
{
    const int v = blockIdx.x * 256 + threadIdx.x;   // float4 index
    float4 s = make_float4(0.f, 0.f, 0.f, 0.f);
#pragma unroll
    for (int ks = 0; ks < KSPLIT; ks++) {
        float4 p = *(const float4*)&g_P[(size_t)ks * (BB * JJ) + v * 4];
        s.x += p.x; s.y += p.y; s.z += p.z; s.w += p.w;
    }
    *(float4*)&g_T[v * 4] = s;
}

// ---------------------------------------------------------------------------
// Kernel 2: fused  z = t @ W_dt + b_dt ; dt = softplus(z) ;
//           y = sum_n exp(A*dt)*h0*C  +  dt*x*sum_n(B*C)  +  x
// Tile 32(b) x 128(d), 256 threads.
// Phase A: GEMM (4b x 4 consecutive d per thread) -> dt, ybase to smem.
// Phase B: h0 sweep, lane l handles (d = dg*8 + l/4, n = (l&3)*4..+3):
//          warp reads 512 contiguous bytes of h0 per float4-load.
// Phase C: coalesced float4 stores.
// Grid (DD/128, BB/32) = (40, 8) = 320 blocks.
// ---------------------------------------------------------------------------
__global__ __launch_bounds__(256) void mamba_ssm_kernel(
    const float* __restrict__ x, const float* __restrict__ h0,
    const float* __restrict__ Wdt, const float* __restrict__ bdt,
    const float* __restrict__ Alog, float* __restrict__ out)
{
    const int d0 = blockIdx.x * 128;
    const int b0 = blockIdx.y * 32;
    const int tid = threadIdx.x;
    const int tdx = tid & 31;     // d lane (owns 4 consecutive d in phase A)
    const int tby = tid >> 5;     // 0..7 (b group / warp id)

    __shared__ float Ts[32][160];    // t tile [b][r] (warp-broadcast reads)
    __shared__ float BCs[32][32];    // B (0..15) and C (16..31) per b
    __shared__ float A2s[128][16];   // -exp(A_log)*log2(e), [d][n]
    __shared__ float Ws[16][128];    // W_dt chunk
    __shared__ float bds[128];
    __shared__ float SBC[32];        // sum_n B[b,n]*C[b,n]
    __shared__ float dts[32][128];   // dt per (b,d)
    __shared__ float ybs[32][128];   // y accumulator per (b,d)

    for (int idx = tid; idx < 32 * 160; idx += 256) {
        int b = idx / 160, r = idx - b * 160;
        Ts[b][r] = g_T[(b0 + b) * JJ + r];
    }
    for (int idx = tid; idx < 32 * 32; idx += 256) {
        int b = idx >> 5, j = idx & 31;
        BCs[b][j] = g_T[(b0 + b) * JJ + RR + j];
    }
    // A2s[d][n], natural layout, vectorized exp
#pragma unroll
    for (int v = tid; v < 512; v += 256) {
        int di = v >> 2, n4 = (v & 3) << 2;
        float4 al = *(const float4*)&Alog[(size_t)(d0 + di) * NN + n4];
        float4 o;
        o.x = -__expf(al.x) * 1.44269504f;
        o.y = -__expf(al.y) * 1.44269504f;
        o.z = -__expf(al.z) * 1.44269504f;
        o.w = -__expf(al.w) * 1.44269504f;
        *(float4*)&A2s[di][n4] = o;
    }
    if (tid < 128) bds[tid] = bdt[d0 + tid];
    __syncthreads();
    if (tid < 32) {
        float s = 0.f;
#pragma unroll
        for (int n = 0; n < NN; n++) s += BCs[tid][n] * BCs[tid][NN + n];
        SBC[tid] = s;
    }
    // SBC visibility guaranteed by the first __syncthreads in the rc loop.

    // ---- Phase A: GEMM ----
    ull acc2[4][2] = {};
    const int wr = tid >> 4;          // 0..15
    const int wc = (tid & 15) << 3;   // 0..120
    for (int rc = 0; rc < RR; rc += 16) {
        const float* wsrc = &Wdt[(size_t)(rc + wr) * DD + d0 + wc];
        float4 w0 = *(const float4*)wsrc;
        float4 w1 = *(const float4*)(wsrc + 4);
        __syncthreads();
        *(float4*)&Ws[wr][wc] = w0;
        *(float4*)&Ws[wr][wc + 4] = w1;
        __syncthreads();
#pragma unroll
        for (int rr = 0; rr < 16; rr++) {
            float4 w4 = *(const float4*)&Ws[rr][tdx * 4];  // conflict-free
            ull w01 = pack2(w4.x, w4.y);
            ull w23 = pack2(w4.z, w4.w);
#pragma unroll
            for (int bi = 0; bi < 4; bi++) {
                float a = Ts[tby * 4 + bi][rc + rr];       // warp broadcast
                ull ap = pack2(a, a);
                acc2[bi][0] = fma2(ap, w01, acc2[bi][0]);
                acc2[bi][1] = fma2(ap, w23, acc2[bi][1]);
            }
        }
    }

    // dt = softplus(z + b_dt); ybase = dt*x*SBC + x  -> stage to smem
    {
        float4 bdv = *(const float4*)&bds[tdx * 4];
#pragma unroll
        for (int bi = 0; bi < 4; bi++) {
            const int bl = tby * 4 + bi;
            float2 p0 = unpk(acc2[bi][0]);
            float2 p1 = unpk(acc2[bi][1]);
            float4 xv = *(const float4*)&x[(size_t)(b0 + bl) * DD + d0 + tdx * 4];
            float z0 = p0.x + bdv.x, z1 = p0.y + bdv.y;
            float z2 = p1.x + bdv.z, z3 = p1.y + bdv.w;
            float4 dtv;
            dtv.x = fmaxf(z0, 0.f) + log1pf(__expf(-fabsf(z0)));
            dtv.y = fmaxf(z1, 0.f) + log1pf(__expf(-fabsf(z1)));
            dtv.z = fmaxf(z2, 0.f) + log1pf(__expf(-fabsf(z2)));
            dtv.w = fmaxf(z3, 0.f) + log1pf(__expf(-fabsf(z3)));
            const float sbc = SBC[bl];
            float4 ybv;
            ybv.x = fmaf(dtv.x * xv.x, sbc, xv.x);
            ybv.y = fmaf(dtv.y * xv.y, sbc, xv.y);
            ybv.z = fmaf(dtv.z * xv.z, sbc, xv.z);
            ybv.w = fmaf(dtv.w * xv.w, sbc, xv.w);
            *(float4*)&dts[bl][tdx * 4] = dtv;
            *(float4*)&ybs[bl][tdx * 4] = ybv;
        }
    }
    __syncthreads();

    // ---- Phase B: coalesced h0 sweep ----
    // 512 warp-iters per block: it -> (b = it>>4, dg = it&15).
    // Lane l: d = dg*8 + (l>>2), n = (l&3)*4 .. +3. Warp reads 512 contiguous B.
    {
        const int lane = tdx;
        const int l4 = lane >> 2;
        const int n4 = (lane & 3) << 2;

        int it = tby;
        const float4* hp =
            (const float4*)&h0[((size_t)(b0 + (it >> 4)) * DD + d0 + (it & 15) * 8 + l4) * NN + n4];
        float4 h = *hp;
#pragma unroll 4
        for (; it < 512; ) {
            const int b = it >> 4, dg = it & 15;
            const int dloc = dg * 8 + l4;
            const int itn = it + 8;
            float4 hn;
            if (itn < 512) {
                hn = *(const float4*)&h0[((size_t)(b0 + (itn >> 4)) * DD + d0 +
                                          (itn & 15) * 8 + l4) * NN + n4];
            }
            const float dt = dts[b][dloc];
            float4 a2 = *(const float4*)&A2s[dloc][n4];
            float4 c4 = *(const float4*)&BCs[b][NN + n4];
            float p0 = ex2f(a2.x * dt) * h.x * c4.x;
            float p1 = ex2f(a2.y * dt) * h.y * c4.y;
            float p2 = ex2f(a2.z * dt) * h.z * c4.z;
            float p3 = ex2f(a2.w * dt) * h.w * c4.w;
            float p = (p0 + p1) + (p2 + p3);
            p += __shfl_xor_sync(0xffffffffu, p, 1);
            p += __shfl_xor_sync(0xffffffffu, p, 2);
            if ((lane & 3) == 0) ybs[b][dloc] += p;
            it = itn;
            h = hn;
        }
    }
    __syncthreads();

    // ---- Phase C: coalesced stores ----
#pragma unroll
    for (int v = tid; v < 1024; v += 256) {
        const int b = v >> 5, c4i = (v & 31) << 2;
        *(float4*)&out[(size_t)(b0 + b) * DD + d0 + c4i] = *(float4*)&ybs[b][c4i];
    }
}

// ---------------------------------------------------------------------------
extern "C" void kernel_launch(void* const* d_in, const int* in_sizes, int n_in,
                              void* d_out, int out_size)
{
    const float* x    = (const float*)d_in[0];
    const float* h0   = (const float*)d_in[1];
    const float* Wx   = (const float*)d_in[2];
    const float* Wdt  = (const float*)d_in[3];
    const float* bdt  = (const float*)d_in[4];
    const float* Wbc  = (const float*)d_in[5];
    const float* Alog = (const float*)d_in[6];
    float* out = (float*)d_out;

    mamba_proj_kernel<<<dim3(4, 3, KSPLIT), 256>>>(x, Wx, Wbc);
    mamba_reduce_kernel<<<(BB * JJ) / 1024, 256>>>();
    mamba_ssm_kernel<<<dim3(DD / 128, BB / 32), 256>>>(x, h0, Wdt, bdt, Alog, out);
}

// round 4
// speedup vs baseline: 1.4630x; 1.0116x over previous
#include <cuda_runtime.h>

#define BB 256
#define DD 5120
#define NN 16
#define RR 160
#define JJ 192          // RR + 32 (B/C projections)
#define KSPLIT 40
#define KCH (DD / KSPLIT)   // 128
#define BK 32

// Scratch (device globals — no allocations allowed)
__device__ float g_P[KSPLIT * BB * JJ];   // split-K partials (7.9 MB)
__device__ float g_T[BB * JJ];            // reduced projections
__device__ float g_DT[BB * DD];           // dt (5.2 MB)

__device__ __forceinline__ float ex2f(float v) {
    float r;
    asm("ex2.approx.ftz.f32 %0, %1;" : "=f"(r) : "f"(v));
    return r;
}

typedef unsigned long long ull;

__device__ __forceinline__ ull fma2(ull a, ull b, ull c) {
    ull d;
    asm("fma.rn.f32x2 %0, %1, %2, %3;" : "=l"(d) : "l"(a), "l"(b), "l"(c));
    return d;
}
__device__ __forceinline__ ull pack2(float x, float y) {
    ull r;
    asm("mov.b64 %0, {%1, %2};" : "=l"(r) : "f"(x), "f"(y));
    return r;
}
__device__ __forceinline__ float2 unpk(ull v) {
    float2 r;
    asm("mov.b64 {%0, %1}, %2;" : "=f"(r.x), "=f"(r.y) : "l"(v));
    return r;
}

// ---------------------------------------------------------------------------
// Kernel 1: split-K GEMM. P[ks] = x[:, k-chunk] @ [W_x_dt | W_BC]
// Tile 64(M) x 64(N), BK=32, 256 threads, 4x4 micro-tile (packed f32x2).
// As stored PRE-DUPLICATED (float2 (v,v)) so a-operands are single LDS.64;
// Bs read as ulonglong2 so b-pairs come free from LDS.128.
// Grid (4, 3, 40) = 480 blocks (single clean wave at ~3.2/SM).
// ---------------------------------------------------------------------------
__global__ __launch_bounds__(256) void mamba_proj_kernel(
    const float* __restrict__ x, const float* __restrict__ Wx,
    const float* __restrict__ Wbc)
{
    __shared__ float2 As2[BK][65];   // [k][m], duplicated, padded
    __shared__ float  Bs[BK][64];    // [k][n]
    const int m0 = blockIdx.x * 64;
    const int n0 = blockIdx.y * 64;
    const int k0 = blockIdx.z * KCH;
    const int tid = threadIdx.x;
    const int tx = tid & 15, ty = tid >> 4;   // micro-tile coords

    // x slab loader coords: float4 idx v -> m = v>>3, k4 = (v&7)*4 (k-fast, coalesced)
    const int am = tid >> 3, ak = (tid & 7) << 2;
    // B slab loader coords: float4 idx v -> kb = v>>4, n4 = (v&15)*4
    const int bk_ = tid >> 4, bn = (tid & 15) << 2;

    ull acc2[4][2] = {};

#pragma unroll
    for (int kc = 0; kc < KCH; kc += BK) {
        const int k = k0 + kc;
        // loads (2 float4 of x, 2 float4 of W per thread)
        float4 av0 = *(const float4*)&x[(size_t)(m0 + am) * DD + k + ak];
        float4 av1 = *(const float4*)&x[(size_t)(m0 + am + 32) * DD + k + ak];
        float4 bv0, bv1;
        {
            const int j = n0 + bn;
            const int kb0 = k + bk_, kb1 = k + bk_ + 16;
            if (j < RR) {
                bv0 = *(const float4*)&Wx[(size_t)kb0 * RR + j];
                bv1 = *(const float4*)&Wx[(size_t)kb1 * RR + j];
            } else {
                bv0 = *(const float4*)&Wbc[(size_t)kb0 * 32 + (j - RR)];
                bv1 = *(const float4*)&Wbc[(size_t)kb1 * 32 + (j - RR)];
            }
        }
        __syncthreads();
        As2[ak + 0][am] = make_float2(av0.x, av0.x);
        As2[ak + 1][am] = make_float2(av0.y, av0.y);
        As2[ak + 2][am] = make_float2(av0.z, av0.z);
        As2[ak + 3][am] = make_float2(av0.w, av0.w);
        As2[ak + 0][am + 32] = make_float2(av1.x, av1.x);
        As2[ak + 1][am + 32] = make_float2(av1.y, av1.y);
        As2[ak + 2][am + 32] = make_float2(av1.z, av1.z);
        As2[ak + 3][am + 32] = make_float2(av1.w, av1.w);
        *(float4*)&Bs[bk_][bn] = bv0;
        *(float4*)&Bs[bk_ + 16][bn] = bv1;
        __syncthreads();
#pragma unroll
        for (int kk = 0; kk < BK; kk++) {
            ulonglong2 bq = *(const ulonglong2*)&Bs[kk][tx * 4];
#pragma unroll
            for (int i = 0; i < 4; i++) {
                ull ad = *(const ull*)&As2[kk][ty * 4 + i];
                acc2[i][0] = fma2(ad, bq.x, acc2[i][0]);
                acc2[i][1] = fma2(ad, bq.y, acc2[i][1]);
            }
        }
    }
    float* dst = &g_P[(size_t)blockIdx.z * (BB * JJ)];
#pragma unroll
    for (int i = 0; i < 4; i++) {
        float2 p0 = unpk(acc2[i][0]);
        float2 p1 = unpk(acc2[i][1]);
        *(float4*)&dst[(size_t)(m0 + ty * 4 + i) * JJ + n0 + tx * 4] =
            make_float4(p0.x, p0.y, p1.x, p1.y);
    }
}

// ---------------------------------------------------------------------------
// Kernel 1r: reduce split-K partials. One thread per float, grid 192.
// ---------------------------------------------------------------------------
__global__ __launch_bounds__(256) void mamba_reduce_kernel()
{
    const int idx = blockIdx.x * 256 + threadIdx.x;
    float s = 0.f;
#pragma unroll
    for (int ks = 0; ks < KSPLIT; ks++) s += g_P[ks * (BB * JJ) + idx];
    g_T[idx] = s;
}

// ---------------------------------------------------------------------------
// Kernel 2a: dt GEMM.  z = t @ W_dt + b_dt ; dt = softplus(z) -> g_DT
// Tile 32(b) x 128(d), 256 threads, 4b x 4 consecutive d per thread.
// smem ~29 KB -> all 320 blocks co-resident.
// ---------------------------------------------------------------------------
__global__ __launch_bounds__(256) void mamba_dt_kernel(
    const float* __restrict__ Wdt, const float* __restrict__ bdt)
{
    const int d0 = blockIdx.x * 128;
    const int b0 = blockIdx.y * 32;
    const int tid = threadIdx.x;
    const int tdx = tid & 31;     // d lane (4 consecutive d)
    const int tby = tid >> 5;     // 0..7 (b group)

    __shared__ float Ts[32][160];    // t tile [b][r] (warp-broadcast reads)
    __shared__ float Ws[16][128];    // W_dt chunk
    __shared__ float bds[128];

    for (int idx = tid; idx < 32 * 160; idx += 256) {
        int b = idx / 160, r = idx - b * 160;
        Ts[b][r] = g_T[(b0 + b) * JJ + r];
    }
    if (tid < 128) bds[tid] = bdt[d0 + tid];

    ull acc2[4][2] = {};
    const int wr = tid >> 4;          // 0..15
    const int wc = (tid & 15) << 3;   // 0..120
    for (int rc = 0; rc < RR; rc += 16) {
        const float* wsrc = &Wdt[(size_t)(rc + wr) * DD + d0 + wc];
        float4 w0 = *(const float4*)wsrc;
        float4 w1 = *(const float4*)(wsrc + 4);
        __syncthreads();
        *(float4*)&Ws[wr][wc] = w0;
        *(float4*)&Ws[wr][wc + 4] = w1;
        __syncthreads();
#pragma unroll
        for (int rr = 0; rr < 16; rr++) {
            ulonglong2 wq = *(const ulonglong2*)&Ws[rr][tdx * 4];  // pairs free
#pragma unroll
            for (int bi = 0; bi < 4; bi++) {
                float a = Ts[tby * 4 + bi][rc + rr];               // broadcast
                ull ap = pack2(a, a);
                acc2[bi][0] = fma2(ap, wq.x, acc2[bi][0]);
                acc2[bi][1] = fma2(ap, wq.y, acc2[bi][1]);
            }
        }
    }

    // dt = softplus(z + b_dt) -> g_DT (coalesced float4)
    float4 bdv = *(const float4*)&bds[tdx * 4];
#pragma unroll
    for (int bi = 0; bi < 4; bi++) {
        const int bl = tby * 4 + bi;
        float2 p0 = unpk(acc2[bi][0]);
        float2 p1 = unpk(acc2[bi][1]);
        float z0 = p0.x + bdv.x, z1 = p0.y + bdv.y;
        float z2 = p1.x + bdv.z, z3 = p1.y + bdv.w;
        float4 dtv;
        dtv.x = fmaxf(z0, 0.f) + log1pf(__expf(-fabsf(z0)));
        dtv.y = fmaxf(z1, 0.f) + log1pf(__expf(-fabsf(z1)));
        dtv.z = fmaxf(z2, 0.f) + log1pf(__expf(-fabsf(z2)));
        dtv.w = fmaxf(z3, 0.f) + log1pf(__expf(-fabsf(z3)));
        *(float4*)&g_DT[(size_t)(b0 + bl) * DD + d0 + tdx * 4] = dtv;
    }
}

// ---------------------------------------------------------------------------
// Kernel 2b: h0 stream.
//   y[b,d] = sum_n ex2(A2[d,n]*dt)*h0[b,d,n]*C[b,n] + dt*x*SBC[b] + x
// Block = (128 d, 16 b). 256 threads, 8 warps. smem ~26 KB.
// Warp-iter: lane l -> (d = dg*8 + l/4, n = (l&3)*4..+3); warp reads 512
// contiguous bytes of h0 per float4 load. Grid (40, 16) = 640 blocks.
// ---------------------------------------------------------------------------
__global__ __launch_bounds__(256) void mamba_scan_kernel(
    const float* __restrict__ x, const float* __restrict__ h0,
    const float* __restrict__ Alog, float* __restrict__ out)
{
    const int d0 = blockIdx.x * 128;
    const int b0 = blockIdx.y * 16;
    const int tid = threadIdx.x;
    const int lane = tid & 31;
    const int w = tid >> 5;

    __shared__ float A2s[128][16];   // -exp(A_log)*log2(e)
    __shared__ float dt_s[16][128];
    __shared__ float Cs[16][16];
    __shared__ float SBCs[16];
    __shared__ float y_s[16][128];   // n-contraction result

    // A2s (vectorized exp), 2048 values
#pragma unroll
    for (int v = tid; v < 512; v += 256) {
        int di = v >> 2, n4 = (v & 3) << 2;
        float4 al = *(const float4*)&Alog[(size_t)(d0 + di) * NN + n4];
        float4 o;
        o.x = -__expf(al.x) * 1.44269504f;
        o.y = -__expf(al.y) * 1.44269504f;
        o.z = -__expf(al.z) * 1.44269504f;
        o.w = -__expf(al.w) * 1.44269504f;
        *(float4*)&A2s[di][n4] = o;
    }
    // dt tile
#pragma unroll
    for (int v = tid; v < 512; v += 256) {
        int b = v >> 5, dq = (v & 31) << 2;
        *(float4*)&dt_s[b][dq] =
            *(const float4*)&g_DT[(size_t)(b0 + b) * DD + d0 + dq];
    }
    // C and SBC
    {
        int b = tid >> 4, n = tid & 15;
        Cs[b][n] = g_T[(b0 + b) * JJ + RR + NN + n];
    }
    if (tid < 16) {
        float s = 0.f;
#pragma unroll
        for (int n = 0; n < NN; n++)
            s += g_T[(b0 + tid) * JJ + RR + n] * g_T[(b0 + tid) * JJ + RR + NN + n];
        SBCs[tid] = s;
    }
    __syncthreads();

    // Main sweep: 256 warp-iters (16 b x 16 d-groups) over 8 warps.
    {
        const int l4 = lane >> 2;
        const int n4 = (lane & 3) << 2;
        int it = w;
        float4 h = *(const float4*)&h0[((size_t)(b0 + (it >> 4)) * DD + d0 +
                                        (it & 15) * 8 + l4) * NN + n4];
        while (it < 256) {
            const int b = it >> 4, dg = it & 15;
            const int dloc = dg * 8 + l4;
            const int itn = it + 8;
            float4 hn;
            if (itn < 256) {
                hn = *(const float4*)&h0[((size_t)(b0 + (itn >> 4)) * DD + d0 +
                                          (itn & 15) * 8 + l4) * NN + n4];
            }
            const float dt = dt_s[b][dloc];
            float4 a2 = *(const float4*)&A2s[dloc][n4];
            float4 c4 = *(const float4*)&Cs[b][n4];
            float p0 = ex2f(a2.x * dt) * h.x * c4.x;
            float p1 = ex2f(a2.y * dt) * h.y * c4.y;
            float p2 = ex2f(a2.z * dt) * h.z * c4.z;
            float p3 = ex2f(a2.w * dt) * h.w * c4.w;
            float p = (p0 + p1) + (p2 + p3);
            p += __shfl_xor_sync(0xffffffffu, p, 1);
            p += __shfl_xor_sync(0xffffffffu, p, 2);
            if ((lane & 3) == 0) y_s[b][dloc] = p;   // exactly-once write
            it = itn;
            h = hn;
        }
    }
    __syncthreads();

    // Combine + coalesced stores: out = y_s + dt*x*SBC + x
#pragma unroll
    for (int v = tid; v < 512; v += 256) {
        const int b = v >> 5, dq = (v & 31) << 2;
        const size_t g = (size_t)(b0 + b) * DD + d0 + dq;
        float4 xv = *(const float4*)&x[g];
        float4 dtv = *(const float4*)&dt_s[b][dq];
        float4 yv = *(const float4*)&y_s[b][dq];
        const float sbc = SBCs[b];
        float4 o;
        o.x = yv.x + fmaf(dtv.x * xv.x, sbc, xv.x);
        o.y = yv.y + fmaf(dtv.y * xv.y, sbc, xv.y);
        o.z = yv.z + fmaf(dtv.z * xv.z, sbc, xv.z);
        o.w = yv.w + fmaf(dtv.w * xv.w, sbc, xv.w);
        *(float4*)&out[g] = o;
    }
}

// ---------------------------------------------------------------------------
extern "C" void kernel_launch(void* const* d_in, const int* in_sizes, int n_in,
                              void* d_out, int out_size)
{
    const float* x    = (const float*)d_in[0];
    const float* h0   = (const float*)d_in[1];
    const float* Wx   = (const float*)d_in[2];
    const float* Wdt  = (const float*)d_in[3];
    const float* bdt  = (const float*)d_in[4];
    const float* Wbc  = (const float*)d_in[5];
    const float* Alog = (const float*)d_in[6];
    float* out = (float*)d_out;

    mamba_proj_kernel<<<dim3(4, 3, KSPLIT), 256>>>(x, Wx, Wbc);
    mamba_reduce_kernel<<<(BB * JJ) / 256, 256>>>();
    mamba_dt_kernel<<<dim3(DD / 128, BB / 32), 256>>>(Wdt, bdt);
    mamba_scan_kernel<<<dim3(DD / 128, BB / 16), 256>>>(x, h0, Alog, out);
}

// round 5
// speedup vs baseline: 1.4655x; 1.0017x over previous
#include <cuda_runtime.h>

#define BB 256
#define DD 5120
#define NN 16
#define RR 160
#define JJ 192          // RR + 32 (B/C projections)
#define KSPLIT 64
#define KCH (DD / KSPLIT)   // 80
#define BK 16

// Scratch (device globals — no allocations allowed)
__device__ float g_P[KSPLIT * BB * JJ];   // split-K partials (12.6 MB)
__device__ float g_T[BB * JJ];            // reduced projections

__device__ __forceinline__ float ex2f(float v) {
    float r;
    asm("ex2.approx.ftz.f32 %0, %1;" : "=f"(r) : "f"(v));
    return r;
}

typedef unsigned long long ull;

__device__ __forceinline__ ull fma2(ull a, ull b, ull c) {
    ull d;
    asm("fma.rn.f32x2 %0, %1, %2, %3;" : "=l"(d) : "l"(a), "l"(b), "l"(c));
    return d;
}
__device__ __forceinline__ ull pack2(float x, float y) {
    ull r;
    asm("mov.b64 %0, {%1, %2};" : "=l"(r) : "f"(x), "f"(y));
    return r;
}
__device__ __forceinline__ float2 unpk(ull v) {
    float2 r;
    asm("mov.b64 {%0, %1}, %2;" : "=f"(r.x), "=f"(r.y) : "l"(v));
    return r;
}

// ---------------------------------------------------------------------------
// Kernel 1: split-K GEMM. P[ks] = x[:, k-chunk] @ [W_x_dt | W_BC]
// Tile 64(M) x 64(N), BK=16, double-buffered smem, one sync per chunk.
// 256 threads, 4x4 micro-tile (packed f32x2), As pre-duplicated.
// Grid (4, 3, 64) = 768 blocks (~5.2/SM, warp-cap 8).
// ---------------------------------------------------------------------------
__global__ __launch_bounds__(256) void mamba_proj_kernel(
    const float* __restrict__ x, const float* __restrict__ Wx,
    const float* __restrict__ Wbc)
{
    __shared__ float2 As2[2][BK][65];   // [buf][k][m], duplicated, padded
    __shared__ float  Bs[2][BK][64];    // [buf][k][n]
    const int m0 = blockIdx.x * 64;
    const int n0 = blockIdx.y * 64;
    const int k0 = blockIdx.z * KCH;
    const int tid = threadIdx.x;
    const int tx = tid & 15, ty = tid >> 4;   // micro-tile coords

    // x loader: one float4/thread: m = tid>>2 (0..63), k4 = (tid&3)*4
    const int am = tid >> 2, ak = (tid & 3) << 2;
    // W loader: one float4/thread: k = tid>>4 (0..15), n4 = (tid&15)*4
    const int bk_ = tid >> 4, bn = (tid & 15) << 2;

    // Branch-free W source (j fixed per thread)
    const int j = n0 + bn;
    const float* bbase;
    size_t bstride;
    if (j < RR) { bbase = Wx + j;        bstride = RR; }
    else        { bbase = Wbc + (j-RR);  bstride = 32; }

    const float* asrc = &x[(size_t)(m0 + am) * DD + k0 + ak];

    ull acc2[4][2] = {};

    // prologue: load + store chunk 0
    float4 av = *(const float4*)asrc;
    float4 bv = *(const float4*)&bbase[(size_t)(k0 + bk_) * bstride];
    As2[0][ak + 0][am] = make_float2(av.x, av.x);
    As2[0][ak + 1][am] = make_float2(av.y, av.y);
    As2[0][ak + 2][am] = make_float2(av.z, av.z);
    As2[0][ak + 3][am] = make_float2(av.w, av.w);
    *(float4*)&Bs[0][bk_][bn] = bv;
    __syncthreads();

#pragma unroll
    for (int c = 0; c < KCH / BK; c++) {
        const int cur = c & 1;
        if (c + 1 < KCH / BK) {
            const int kn = k0 + (c + 1) * BK;
            av = *(const float4*)(asrc + (c + 1) * BK);
            bv = *(const float4*)&bbase[(size_t)(kn + bk_) * bstride];
        }
#pragma unroll
        for (int kk = 0; kk < BK; kk++) {
            ulonglong2 bq = *(const ulonglong2*)&Bs[cur][kk][tx * 4];
#pragma unroll
            for (int i = 0; i < 4; i++) {
                ull ad = *(const ull*)&As2[cur][kk][ty * 4 + i];
                acc2[i][0] = fma2(ad, bq.x, acc2[i][0]);
                acc2[i][1] = fma2(ad, bq.y, acc2[i][1]);
            }
        }
        if (c + 1 < KCH / BK) {
            const int nxt = cur ^ 1;
            As2[nxt][ak + 0][am] = make_float2(av.x, av.x);
            As2[nxt][ak + 1][am] = make_float2(av.y, av.y);
            As2[nxt][ak + 2][am] = make_float2(av.z, av.z);
            As2[nxt][ak + 3][am] = make_float2(av.w, av.w);
            *(float4*)&Bs[nxt][bk_][bn] = bv;
            __syncthreads();
        }
    }

    float* dst = &g_P[(size_t)blockIdx.z * (BB * JJ)];
#pragma unroll
    for (int i = 0; i < 4; i++) {
        float2 p0 = unpk(acc2[i][0]);
        float2 p1 = unpk(acc2[i][1]);
        *(float4*)&dst[(size_t)(m0 + ty * 4 + i) * JJ + n0 + tx * 4] =
            make_float4(p0.x, p0.y, p1.x, p1.y);
    }
}

// ---------------------------------------------------------------------------
// Kernel 1r: reduce split-K partials. One thread per float, grid 192.
// ---------------------------------------------------------------------------
__global__ __launch_bounds__(256) void mamba_reduce_kernel()
{
    const int idx = blockIdx.x * 256 + threadIdx.x;
    float s = 0.f;
#pragma unroll 16
    for (int ks = 0; ks < KSPLIT; ks++) s += g_P[ks * (BB * JJ) + idx];
    g_T[idx] = s;
}

// ---------------------------------------------------------------------------
// Kernel 2 (fused): per block (16 b x 128 d):
//   Phase A: z = t @ W_dt + b_dt ; dt = softplus(z) -> smem
//   Phase B: coalesced h0 sweep, n-contraction via shfl
//   Phase C: out = y + dt*x*SBC + x  (coalesced float4)
// 256 threads, smem ~45 KB -> 5 blocks/SM -> all 640 blocks in one wave.
// Grid (DD/128, BB/16) = (40, 16).
// ---------------------------------------------------------------------------
__global__ __launch_bounds__(256) void mamba_scan_kernel(
    const float* __restrict__ x, const float* __restrict__ h0,
    const float* __restrict__ Wdt, const float* __restrict__ bdt,
    const float* __restrict__ Alog, float* __restrict__ out)
{
    const int d0 = blockIdx.x * 128;
    const int b0 = blockIdx.y * 16;
    const int tid = threadIdx.x;
    const int lane = tid & 31;
    const int w = tid >> 5;          // warp 0..7

    __shared__ float Ts[16][160];    // t tile [b][r]
    __shared__ float Ws[16][128];    // W_dt chunk
    __shared__ float A2s[128][16];   // -exp(A_log)*log2(e)
    __shared__ float dt_s[16][128];
    __shared__ float y_s[16][128];
    __shared__ float Cs[16][16];
    __shared__ float SBCs[16];
    __shared__ float bds[128];

    // --- stage block-constant data ---
    // Ts: 640 float4s (g_T rows are 192 floats; r<160 is float4-aligned)
    for (int v = tid; v < 640; v += 256) {
        int b = v / 40, r4 = (v - b * 40) * 4;
        *(float4*)&Ts[b][r4] = *(const float4*)&g_T[(b0 + b) * JJ + r4];
    }
    // A2s
#pragma unroll
    for (int v = tid; v < 512; v += 256) {
        int di = v >> 2, n4 = (v & 3) << 2;
        float4 al = *(const float4*)&Alog[(size_t)(d0 + di) * NN + n4];
        float4 o;
        o.x = -__expf(al.x) * 1.44269504f;
        o.y = -__expf(al.y) * 1.44269504f;
        o.z = -__expf(al.z) * 1.44269504f;
        o.w = -__expf(al.w) * 1.44269504f;
        *(float4*)&A2s[di][n4] = o;
    }
    // C, SBC, b_dt
    {
        int b = tid >> 4, n = tid & 15;
        Cs[b][n] = g_T[(b0 + b) * JJ + RR + NN + n];
    }
    if (tid < 16) {
        float s = 0.f;
#pragma unroll
        for (int n = 0; n < NN; n++)
            s += g_T[(b0 + tid) * JJ + RR + n] * g_T[(b0 + tid) * JJ + RR + NN + n];
        SBCs[tid] = s;
    }
    if (tid < 128) bds[tid] = bdt[d0 + tid];

    // ---- Phase A: GEMM (M=16, N=128, K=160), thread owns 2b x 4d ----
    const int tdx = lane;            // d lane: d = tdx*4 .. +3
    ull acc2[2][2] = {};
    const int wr = tid >> 4;          // 0..15
    const int wc = (tid & 15) << 3;   // 0..120
    for (int rc = 0; rc < RR; rc += 16) {
        const float* wsrc = &Wdt[(size_t)(rc + wr) * DD + d0 + wc];
        float4 w0 = *(const float4*)wsrc;      // LDG overlaps prior compute
        float4 w1 = *(const float4*)(wsrc + 4);
        __syncthreads();
        *(float4*)&Ws[wr][wc] = w0;
        *(float4*)&Ws[wr][wc + 4] = w1;
        __syncthreads();
#pragma unroll
        for (int rr = 0; rr < 16; rr++) {
            ulonglong2 wq = *(const ulonglong2*)&Ws[rr][tdx * 4];
            float a0 = Ts[w * 2 + 0][rc + rr];   // broadcast
            float a1 = Ts[w * 2 + 1][rc + rr];
            ull ap0 = pack2(a0, a0), ap1 = pack2(a1, a1);
            acc2[0][0] = fma2(ap0, wq.x, acc2[0][0]);
            acc2[0][1] = fma2(ap0, wq.y, acc2[0][1]);
            acc2[1][0] = fma2(ap1, wq.x, acc2[1][0]);
            acc2[1][1] = fma2(ap1, wq.y, acc2[1][1]);
        }
    }
    // softplus -> dt_s
    {
        float4 bdv = *(const float4*)&bds[tdx * 4];
#pragma unroll
        for (int bi = 0; bi < 2; bi++) {
            float2 p0 = unpk(acc2[bi][0]);
            float2 p1 = unpk(acc2[bi][1]);
            float z0 = p0.x + bdv.x, z1 = p0.y + bdv.y;
            float z2 = p1.x + bdv.z, z3 = p1.y + bdv.w;
            float4 dtv;
            dtv.x = fmaxf(z0, 0.f) + log1pf(__expf(-fabsf(z0)));
            dtv.y = fmaxf(z1, 0.f) + log1pf(__expf(-fabsf(z1)));
            dtv.z = fmaxf(z2, 0.f) + log1pf(__expf(-fabsf(z2)));
            dtv.w = fmaxf(z3, 0.f) + log1pf(__expf(-fabsf(z3)));
            *(float4*)&dt_s[w * 2 + bi][tdx * 4] = dtv;
        }
    }
    __syncthreads();

    // ---- Phase B: h0 sweep. Warp w owns b in {2w, 2w+1}; per b it streams
    // a contiguous 8 KB region (16 dg-steps x 512 B). Lane l handles
    // (d = dg*8 + l/4, n = (l&3)*4..+3). ----
    {
        const int l4 = lane >> 2;
        const int n4 = (lane & 3) << 2;
#pragma unroll
        for (int bi = 0; bi < 2; bi++) {
            const int b = w * 2 + bi;
            const float* hp = &h0[((size_t)(b0 + b) * DD + d0 + l4) * NN + n4];
            float4 h = __ldcs((const float4*)hp);
#pragma unroll 4
            for (int dg = 0; dg < 16; dg++) {
                float4 hn;
                if (dg < 15) hn = __ldcs((const float4*)(hp + (size_t)(dg + 1) * 128));
                const int dloc = dg * 8 + l4;
                const float dt = dt_s[b][dloc];
                float4 a2 = *(const float4*)&A2s[dloc][n4];
                float4 c4 = *(const float4*)&Cs[b][n4];
                float p0 = ex2f(a2.x * dt) * h.x * c4.x;
                float p1 = ex2f(a2.y * dt) * h.y * c4.y;
                float p2 = ex2f(a2.z * dt) * h.z * c4.z;
                float p3 = ex2f(a2.w * dt) * h.w * c4.w;
                float p = (p0 + p1) + (p2 + p3);
                p += __shfl_xor_sync(0xffffffffu, p, 1);
                p += __shfl_xor_sync(0xffffffffu, p, 2);
                if ((lane & 3) == 0) y_s[b][dloc] = p;
                h = hn;
            }
        }
    }
    __syncthreads();

    // ---- Phase C: combine + coalesced stores ----
#pragma unroll
    for (int v = tid; v < 512; v += 256) {
        const int b = v >> 5, dq = (v & 31) << 2;
        const size_t g = (size_t)(b0 + b) * DD + d0 + dq;
        float4 xv = *(const float4*)&x[g];
        float4 dtv = *(const float4*)&dt_s[b][dq];
        float4 yv = *(const float4*)&y_s[b][dq];
        const float sbc = SBCs[b];
        float4 o;
        o.x = yv.x + fmaf(dtv.x * xv.x, sbc, xv.x);
        o.y = yv.y + fmaf(dtv.y * xv.y, sbc, xv.y);
        o.z = yv.z + fmaf(dtv.z * xv.z, sbc, xv.z);
        o.w = yv.w + fmaf(dtv.w * xv.w, sbc, xv.w);
        *(float4*)&out[g] = o;
    }
}

// ---------------------------------------------------------------------------
extern "C" void kernel_launch(void* const* d_in, const int* in_sizes, int n_in,
                              void* d_out, int out_size)
{
    const float* x    = (const float*)d_in[0];
    const float* h0   = (const float*)d_in[1];
    const float* Wx   = (const float*)d_in[2];
    const float* Wdt  = (const float*)d_in[3];
    const float* bdt  = (const float*)d_in[4];
    const float* Wbc  = (const float*)d_in[5];
    const float* Alog = (const float*)d_in[6];
    float* out = (float*)d_out;

    mamba_proj_kernel<<<dim3(4, 3, KSPLIT), 256>>>(x, Wx, Wbc);
    mamba_reduce_kernel<<<(BB * JJ) / 256, 256>>>();
    mamba_scan_kernel<<<dim3(DD / 128, BB / 16), 256>>>(x, h0, Wdt, bdt, Alog, out);
}

// round 6
// speedup vs baseline: 1.6060x; 1.0959x over previous
#include <cuda_runtime.h>

#define BB 256
#define DD 5120
#define NN 16
#define RR 160
#define JJ 192          // RR + 32 (B/C projections)
#define KSPLIT 64
#define KCH (DD / KSPLIT)   // 80
#define BK 16

// Scratch (device globals — no allocations allowed)
__device__ float g_P[KSPLIT * BB * JJ];   // split-K partials (12.6 MB)
__device__ float g_T[BB * JJ];            // reduced projections
__device__ float g_DT[BB * DD];           // dt (5.2 MB)

__device__ __forceinline__ float ex2f(float v) {
    float r;
    asm("ex2.approx.ftz.f32 %0, %1;" : "=f"(r) : "f"(v));
    return r;
}

typedef unsigned long long ull;

__device__ __forceinline__ ull fma2(ull a, ull b, ull c) {
    ull d;
    asm("fma.rn.f32x2 %0, %1, %2, %3;" : "=l"(d) : "l"(a), "l"(b), "l"(c));
    return d;
}
__device__ __forceinline__ float2 unpk(ull v) {
    float2 r;
    asm("mov.b64 {%0, %1}, %2;" : "=f"(r.x), "=f"(r.y) : "l"(v));
    return r;
}

// ---------------------------------------------------------------------------
// Kernel 1: split-K GEMM. P[ks] = x[:, k-chunk] @ [W_x_dt | W_BC]
// Tile 128(M) x 64(N), BK=16, double-buffered, 256 threads.
// Micro-tile 8M x 4N. As stored [k][m] DUPLICATED (float2 (v,v)): one
// LDS.128 yields TWO FFMA2-ready a-operands -> 1.25 smem B/FMA, zero MOVs.
// Grid (2, 3, 64) = 384 blocks (~2.6/SM, all resident).
// ---------------------------------------------------------------------------
__global__ __launch_bounds__(256) void mamba_proj_kernel(
    const float* __restrict__ x, const float* __restrict__ Wx,
    const float* __restrict__ Wbc)
{
    __shared__ float2 As2[2][BK][130];  // [buf][k][m] duplicated, padded (even)
    __shared__ float  Bs[2][BK][64];    // [buf][k][n]
    const int m0 = blockIdx.x * 128;
    const int n0 = blockIdx.y * 64;
    const int k0 = blockIdx.z * KCH;
    const int tid = threadIdx.x;
    const int tx = tid & 15, ty = tid >> 4;   // micro coords: n=tx*4, m=ty*8

    // A loader: 2 float4/thread: m = v>>2 (0..127), kq = (v&3)*4
    const int am = tid >> 2, akq = (tid & 3) << 2;
    // B loader: 1 float4/thread: k = tid>>4, n4 = (tid&15)*4
    const int bk_ = tid >> 4, bn = (tid & 15) << 2;

    // Branch-free W source (column j fixed per thread)
    const int j = n0 + bn;
    const float* bbase;
    size_t bstride;
    if (j < RR) { bbase = Wx + j;         bstride = RR; }
    else        { bbase = Wbc + (j - RR); bstride = 32; }

    const float* a0src = &x[(size_t)(m0 + am) * DD + k0 + akq];
    const float* a1src = a0src + (size_t)64 * DD;

    ull acc2[8][2] = {};

    // prologue: chunk 0
    float4 av0 = *(const float4*)a0src;
    float4 av1 = *(const float4*)a1src;
    float4 bv  = *(const float4*)&bbase[(size_t)(k0 + bk_) * bstride];
#pragma unroll
    for (int q = 0; q < 4; q++) {
        float a0 = ((const float*)&av0)[q], a1 = ((const float*)&av1)[q];
        As2[0][akq + q][am]      = make_float2(a0, a0);
        As2[0][akq + q][am + 64] = make_float2(a1, a1);
    }
    *(float4*)&Bs[0][bk_][bn] = bv;
    __syncthreads();

#pragma unroll
    for (int c = 0; c < KCH / BK; c++) {
        const int cur = c & 1;
        if (c + 1 < KCH / BK) {
            av0 = *(const float4*)(a0src + (c + 1) * BK);
            av1 = *(const float4*)(a1src + (c + 1) * BK);
            bv  = *(const float4*)&bbase[(size_t)(k0 + (c + 1) * BK + bk_) * bstride];
        }
#pragma unroll
        for (int kk = 0; kk < BK; kk++) {
            ulonglong2 bq = *(const ulonglong2*)&Bs[cur][kk][tx * 4];
            ulonglong2 aq0 = *(const ulonglong2*)&As2[cur][kk][ty * 8 + 0];
            ulonglong2 aq1 = *(const ulonglong2*)&As2[cur][kk][ty * 8 + 2];
            ulonglong2 aq2 = *(const ulonglong2*)&As2[cur][kk][ty * 8 + 4];
            ulonglong2 aq3 = *(const ulonglong2*)&As2[cur][kk][ty * 8 + 6];
            acc2[0][0] = fma2(aq0.x, bq.x, acc2[0][0]);
            acc2[0][1] = fma2(aq0.x, bq.y, acc2[0][1]);
            acc2[1][0] = fma2(aq0.y, bq.x, acc2[1][0]);
            acc2[1][1] = fma2(aq0.y, bq.y, acc2[1][1]);
            acc2[2][0] = fma2(aq1.x, bq.x, acc2[2][0]);
            acc2[2][1] = fma2(aq1.x, bq.y, acc2[2][1]);
            acc2[3][0] = fma2(aq1.y, bq.x, acc2[3][0]);
            acc2[3][1] = fma2(aq1.y, bq.y, acc2[3][1]);
            acc2[4][0] = fma2(aq2.x, bq.x, acc2[4][0]);
            acc2[4][1] = fma2(aq2.x, bq.y, acc2[4][1]);
            acc2[5][0] = fma2(aq2.y, bq.x, acc2[5][0]);
            acc2[5][1] = fma2(aq2.y, bq.y, acc2[5][1]);
            acc2[6][0] = fma2(aq3.x, bq.x, acc2[6][0]);
            acc2[6][1] = fma2(aq3.x, bq.y, acc2[6][1]);
            acc2[7][0] = fma2(aq3.y, bq.x, acc2[7][0]);
            acc2[7][1] = fma2(aq3.y, bq.y, acc2[7][1]);
        }
        if (c + 1 < KCH / BK) {
            const int nxt = cur ^ 1;
            __syncthreads();
#pragma unroll
            for (int q = 0; q < 4; q++) {
                float a0 = ((const float*)&av0)[q], a1 = ((const float*)&av1)[q];
                As2[nxt][akq + q][am]      = make_float2(a0, a0);
                As2[nxt][akq + q][am + 64] = make_float2(a1, a1);
            }
            *(float4*)&Bs[nxt][bk_][bn] = bv;
            __syncthreads();
        }
    }

    float* dst = &g_P[(size_t)blockIdx.z * (BB * JJ)];
#pragma unroll
    for (int i = 0; i < 8; i++) {
        float2 p0 = unpk(acc2[i][0]);
        float2 p1 = unpk(acc2[i][1]);
        *(float4*)&dst[(size_t)(m0 + ty * 8 + i) * JJ + n0 + tx * 4] =
            make_float4(p0.x, p0.y, p1.x, p1.y);
    }
}

// ---------------------------------------------------------------------------
// Kernel 1r: reduce split-K partials. One thread per float, grid 192.
// ---------------------------------------------------------------------------
__global__ __launch_bounds__(256) void mamba_reduce_kernel()
{
    const int idx = blockIdx.x * 256 + threadIdx.x;
    float s = 0.f;
#pragma unroll 16
    for (int ks = 0; ks < KSPLIT; ks++) s += g_P[ks * (BB * JJ) + idx];
    g_T[idx] = s;
}

// ---------------------------------------------------------------------------
// Kernel 2a: dt GEMM.  z = t @ W_dt + b_dt ; dt = softplus(z) -> g_DT
// Tile 32(b) x 128(d), 256 threads, thread owns 4b x 4 consecutive d.
// Ts stored PRE-DUPLICATED: broadcast LDS.64 is directly the FFMA2 operand
// (no pack MOVs). 13 inst / 32 FMA in the inner loop. Grid (40, 8).
// ---------------------------------------------------------------------------
__global__ __launch_bounds__(256) void mamba_dt_kernel(
    const float* __restrict__ Wdt, const float* __restrict__ bdt)
{
    const int d0 = blockIdx.x * 128;
    const int b0 = blockIdx.y * 32;
    const int tid = threadIdx.x;
    const int tdx = tid & 31;     // d lane (4 consecutive d)
    const int tby = tid >> 5;     // warp id = b group (4 b per warp)

    __shared__ float2 Ts2[32][160];  // t tile, duplicated (41 KB)
    __shared__ float  Ws[16][128];   // W_dt chunk
    __shared__ float  bds[128];

    // Ts2 loader: 1280 float4 of g_T -> duplicated float2 stores
    for (int v = tid; v < 1280; v += 256) {
        int b = v / 40, r4 = (v - b * 40) * 4;
        float4 t4 = *(const float4*)&g_T[(b0 + b) * JJ + r4];
        Ts2[b][r4 + 0] = make_float2(t4.x, t4.x);
        Ts2[b][r4 + 1] = make_float2(t4.y, t4.y);
        Ts2[b][r4 + 2] = make_float2(t4.z, t4.z);
        Ts2[b][r4 + 3] = make_float2(t4.w, t4.w);
    }
    if (tid < 128) bds[tid] = bdt[d0 + tid];

    ull acc2[4][2] = {};
    const int wr = tid >> 4;          // 0..15
    const int wc = (tid & 15) << 3;   // 0..120
    for (int rc = 0; rc < RR; rc += 16) {
        const float* wsrc = &Wdt[(size_t)(rc + wr) * DD + d0 + wc];
        float4 w0 = *(const float4*)wsrc;
        float4 w1 = *(const float4*)(wsrc + 4);
        __syncthreads();
        *(float4*)&Ws[wr][wc] = w0;
        *(float4*)&Ws[wr][wc + 4] = w1;
        __syncthreads();
#pragma unroll
        for (int rr = 0; rr < 16; rr++) {
            ulonglong2 wq = *(const ulonglong2*)&Ws[rr][tdx * 4];
            ull a0 = *(const ull*)&Ts2[tby * 4 + 0][rc + rr];  // bcast LDS.64
            ull a1 = *(const ull*)&Ts2[tby * 4 + 1][rc + rr];
            ull a2 = *(const ull*)&Ts2[tby * 4 + 2][rc + rr];
            ull a3 = *(const ull*)&Ts2[tby * 4 + 3][rc + rr];
            acc2[0][0] = fma2(a0, wq.x, acc2[0][0]);
            acc2[0][1] = fma2(a0, wq.y, acc2[0][1]);
            acc2[1][0] = fma2(a1, wq.x, acc2[1][0]);
            acc2[1][1] = fma2(a1, wq.y, acc2[1][1]);
            acc2[2][0] = fma2(a2, wq.x, acc2[2][0]);
            acc2[2][1] = fma2(a2, wq.y, acc2[2][1]);
            acc2[3][0] = fma2(a3, wq.x, acc2[3][0]);
            acc2[3][1] = fma2(a3, wq.y, acc2[3][1]);
        }
    }

    // dt = softplus(z + b_dt) -> g_DT (coalesced float4)
    float4 bdv = *(const float4*)&bds[tdx * 4];
#pragma unroll
    for (int bi = 0; bi < 4; bi++) {
        const int bl = tby * 4 + bi;
        float2 p0 = unpk(acc2[bi][0]);
        float2 p1 = unpk(acc2[bi][1]);
        float z0 = p0.x + bdv.x, z1 = p0.y + bdv.y;
        float z2 = p1.x + bdv.z, z3 = p1.y + bdv.w;
        float4 dtv;
        dtv.x = fmaxf(z0, 0.f) + log1pf(__expf(-fabsf(z0)));
        dtv.y = fmaxf(z1, 0.f) + log1pf(__expf(-fabsf(z1)));
        dtv.z = fmaxf(z2, 0.f) + log1pf(__expf(-fabsf(z2)));
        dtv.w = fmaxf(z3, 0.f) + log1pf(__expf(-fabsf(z3)));
        *(float4*)&g_DT[(size_t)(b0 + bl) * DD + d0 + tdx * 4] = dtv;
    }
}

// ---------------------------------------------------------------------------
// Kernel 2b: h0 stream (proven R4 structure + contiguous per-warp streams).
//   y[b,d] = sum_n ex2(A2[d,n]*dt)*h0[b,d,n]*C[b,n] + dt*x*SBC[b] + x
// Block = (128 d, 16 b), 256 threads, 8 warps; warp owns b in {2w, 2w+1},
// streams a contiguous 8 KB h0 region per b. Grid (40, 16) = 640 blocks.
// ---------------------------------------------------------------------------
__global__ __launch_bounds__(256) void mamba_scan_kernel(
    const float* __restrict__ x, const float* __restrict__ h0,
    const float* __restrict__ Alog, float* __restrict__ out)
{
    const int d0 = blockIdx.x * 128;
    const int b0 = blockIdx.y * 16;
    const int tid = threadIdx.x;
    const int lane = tid & 31;
    const int w = tid >> 5;

    __shared__ float A2s[128][16];   // -exp(A_log)*log2(e)
    __shared__ float dt_s[16][128];
    __shared__ float y_s[16][128];
    __shared__ float Cs[16][16];
    __shared__ float SBCs[16];

    // A2s (vectorized exp)
#pragma unroll
    for (int v = tid; v < 512; v += 256) {
        int di = v >> 2, n4 = (v & 3) << 2;
        float4 al = *(const float4*)&Alog[(size_t)(d0 + di) * NN + n4];
        float4 o;
        o.x = -__expf(al.x) * 1.44269504f;
        o.y = -__expf(al.y) * 1.44269504f;
        o.z = -__expf(al.z) * 1.44269504f;
        o.w = -__expf(al.w) * 1.44269504f;
        *(float4*)&A2s[di][n4] = o;
    }
    // dt tile
#pragma unroll
    for (int v = tid; v < 512; v += 256) {
        int b = v >> 5, dq = (v & 31) << 2;
        *(float4*)&dt_s[b][dq] =
            *(const float4*)&g_DT[(size_t)(b0 + b) * DD + d0 + dq];
    }
    // C, SBC
    {
        int b = tid >> 4, n = tid & 15;
        Cs[b][n] = g_T[(b0 + b) * JJ + RR + NN + n];
    }
    if (tid < 16) {
        float s = 0.f;
#pragma unroll
        for (int n = 0; n < NN; n++)
            s += g_T[(b0 + tid) * JJ + RR + n] * g_T[(b0 + tid) * JJ + RR + NN + n];
        SBCs[tid] = s;
    }
    __syncthreads();

    // Coalesced h0 sweep: lane l -> (d = dg*8 + l/4, n = (l&3)*4..+3).
    {
        const int l4 = lane >> 2;
        const int n4 = (lane & 3) << 2;
#pragma unroll
        for (int bi = 0; bi < 2; bi++) {
            const int b = w * 2 + bi;
            const float* hp = &h0[((size_t)(b0 + b) * DD + d0 + l4) * NN + n4];
            float4 h = __ldcs((const float4*)hp);
#pragma unroll 4
            for (int dg = 0; dg < 16; dg++) {
                float4 hn;
                if (dg < 15) hn = __ldcs((const float4*)(hp + (size_t)(dg + 1) * 128));
                const int dloc = dg * 8 + l4;
                const float dt = dt_s[b][dloc];
                float4 a2 = *(const float4*)&A2s[dloc][n4];
                float4 c4 = *(const float4*)&Cs[b][n4];
                float p0 = ex2f(a2.x * dt) * h.x * c4.x;
                float p1 = ex2f(a2.y * dt) * h.y * c4.y;
                float p2 = ex2f(a2.z * dt) * h.z * c4.z;
                float p3 = ex2f(a2.w * dt) * h.w * c4.w;
                float p = (p0 + p1) + (p2 + p3);
                p += __shfl_xor_sync(0xffffffffu, p, 1);
                p += __shfl_xor_sync(0xffffffffu, p, 2);
                if ((lane & 3) == 0) y_s[b][dloc] = p;
                h = hn;
            }
        }
    }
    __syncthreads();

    // Combine + coalesced stores: out = y + dt*x*SBC + x
#pragma unroll
    for (int v = tid; v < 512; v += 256) {
        const int b = v >> 5, dq = (v & 31) << 2;
        const size_t g = (size_t)(b0 + b) * DD + d0 + dq;
        float4 xv = *(const float4*)&x[g];
        float4 dtv = *(const float4*)&dt_s[b][dq];
        float4 yv = *(const float4*)&y_s[b][dq];
        const float sbc = SBCs[b];
        float4 o;
        o.x = yv.x + fmaf(dtv.x * xv.x, sbc, xv.x);
        o.y = yv.y + fmaf(dtv.y * xv.y, sbc, xv.y);
        o.z = yv.z + fmaf(dtv.z * xv.z, sbc, xv.z);
        o.w = yv.w + fmaf(dtv.w * xv.w, sbc, xv.w);
        *(float4*)&out[g] = o;
    }
}

// ---------------------------------------------------------------------------
extern "C" void kernel_launch(void* const* d_in, const int* in_sizes, int n_in,
                              void* d_out, int out_size)
{
    const float* x    = (const float*)d_in[0];
    const float* h0   = (const float*)d_in[1];
    const float* Wx   = (const float*)d_in[2];
    const float* Wdt  = (const float*)d_in[3];
    const float* bdt  = (const float*)d_in[4];
    const float* Wbc  = (const float*)d_in[5];
    const float* Alog = (const float*)d_in[6];
    float* out = (float*)d_out;

    mamba_proj_kernel<<<dim3(2, 3, KSPLIT), 256>>>(x, Wx, Wbc);
    mamba_reduce_kernel<<<(BB * JJ) / 256, 256>>>();
    mamba_dt_kernel<<<dim3(DD / 128, BB / 32), 256>>>(Wdt, bdt);
    mamba_scan_kernel<<<dim3(DD / 128, BB / 16), 256>>>(x, h0, Alog, out);
}